// round 8
// baseline (speedup 1.0000x reference)
#include <cuda_runtime.h>
#include <cuda_fp16.h>
#include <cstdint>

#define NT 256
#define HD 128
#define BQ 128
#define BK 64

#define NELEM (16 * 2048 * 128)

// fp16 scratch (static device memory — not an allocation)
__device__ __half g_qh[NELEM];
__device__ __half g_kh[NELEM];
__device__ __half g_vh[NELEM];

// ---- smem layout (byte offsets) ----
#define Q_O  0            // 128 rows x 256B fp16 (swizzled)      = 32768
#define K_O  32768        // 2 x [64][128] fp16 swizzled          = 32768
#define KBUF 16384
#define V_O  65536        // 2 x [64][128] fp16 swizzled (k-major)= 32768
#define VBUF 16384
#define M_O  98304        // 2048 floats, premultiplied mask      = 8192
#define SMEM_BYTES 106496

__device__ __forceinline__ uint32_t smem_u32(const void* p) {
    uint32_t a;
    asm("{ .reg .u64 t; cvta.to.shared.u64 t, %1; cvt.u32.u64 %0, t; }" : "=r"(a) : "l"(p));
    return a;
}

__device__ __forceinline__ void ldsm4(uint32_t r[4], uint32_t addr) {
    asm volatile("ldmatrix.sync.aligned.m8n8.x4.shared.b16 {%0,%1,%2,%3}, [%4];"
                 : "=r"(r[0]), "=r"(r[1]), "=r"(r[2]), "=r"(r[3]) : "r"(addr));
}
__device__ __forceinline__ void ldsm4t(uint32_t r[4], uint32_t addr) {
    asm volatile("ldmatrix.sync.aligned.m8n8.x4.trans.shared.b16 {%0,%1,%2,%3}, [%4];"
                 : "=r"(r[0]), "=r"(r[1]), "=r"(r[2]), "=r"(r[3]) : "r"(addr));
}

__device__ __forceinline__ void mma16(float d[4], const uint32_t a[4],
                                      uint32_t b0, uint32_t b1) {
    asm volatile("mma.sync.aligned.m16n8k16.row.col.f32.f16.f16.f32 "
                 "{%0,%1,%2,%3}, {%4,%5,%6,%7}, {%8,%9}, {%0,%1,%2,%3};"
                 : "+f"(d[0]), "+f"(d[1]), "+f"(d[2]), "+f"(d[3])
                 : "r"(a[0]), "r"(a[1]), "r"(a[2]), "r"(a[3]), "r"(b0), "r"(b1));
}

__device__ __forceinline__ float ex2f(float x) {
    float r; asm("ex2.approx.ftz.f32 %0, %1;" : "=f"(r) : "f"(x)); return r;
}

__device__ __forceinline__ uint2 cvt4_hi(float4 f) {
    __half2 h01 = __floats2half2_rn(f.x, f.y);
    __half2 h23 = __floats2half2_rn(f.z, f.w);
    uint2 r;
    r.x = *reinterpret_cast<uint32_t*>(&h01);
    r.y = *reinterpret_cast<uint32_t*>(&h23);
    return r;
}

#define CPA16(dst, src) \
    asm volatile("cp.async.ca.shared.global [%0], [%1], 16;" :: "r"(dst), "l"(src))
#define CPA_COMMIT() asm volatile("cp.async.commit_group;")
#define CPA_WAIT0()  asm volatile("cp.async.wait_group 0;" ::: "memory")

// ================= pre-pass: fp32 -> fp16 =================
__global__ void __launch_bounds__(256, 8)
cvt3_kernel(const float4* __restrict__ q, const float4* __restrict__ k,
            const float4* __restrict__ v, int n4)
{
    int i = blockIdx.x * 256 + threadIdx.x;
    if (i < n4) {
        reinterpret_cast<uint2*>(g_qh)[i] = cvt4_hi(q[i]);
        reinterpret_cast<uint2*>(g_kh)[i] = cvt4_hi(k[i]);
        reinterpret_cast<uint2*>(g_vh)[i] = cvt4_hi(v[i]);
    }
}

// ================= main kernel =================
__global__ void __launch_bounds__(NT, 2)
fa_cp_kernel(const float* __restrict__ mask, float* __restrict__ Out,
             int Lq, int Lk)
{
    extern __shared__ char sm8[];
    const uint32_t su = smem_u32(sm8);

    const int tid  = threadIdx.x;
    const int lane = tid & 31;
    const int wid  = tid >> 5;
    const int m0   = wid << 4;
    const int b    = blockIdx.y;
    const int q0   = blockIdx.x * BQ;

    const int lr = lane & 7;
    const int g  = lane >> 3;

    const float C1 = 0.0883883476483184405f * 1.44269504088896341f;
    const float C2 = -1.44269504088896341e9f;

    const __half* Qg = g_qh + ((size_t)b * Lq + q0) * HD;
    const __half* Kg = g_kh + (size_t)b * Lk * HD;
    const __half* Vg = g_vh + (size_t)b * Lk * HD;
    const int ntiles = Lk / BK;

    // ---------------- prologue ----------------
    float* msm = (float*)(sm8 + M_O);
#pragma unroll
    for (int i = 0; i < 8; i++)
        msm[tid + NT * i] = mask[tid + NT * i] * C2;

    // Q tile: 128 rows x 16 chunks of 16B
#pragma unroll
    for (int i = 0; i < 8; i++) {
        int idx = tid + NT * i;
        int row = idx >> 4, cc = idx & 15;
        CPA16(su + Q_O + row * 256 + ((cc ^ (row & 7)) << 4),
              Qg + row * HD + cc * 8);
    }
    // K(0), V(0): 64 rows x 16 chunks each
#pragma unroll
    for (int i = 0; i < 4; i++) {
        int idx = tid + NT * i;
        int row = idx >> 4, cc = idx & 15;
        uint32_t o = row * 256 + ((cc ^ (row & 7)) << 4);
        CPA16(su + K_O + o, Kg + row * HD + cc * 8);
        CPA16(su + V_O + o, Vg + row * HD + cc * 8);
    }
    CPA_COMMIT();
    CPA_WAIT0();
    __syncthreads();

    // per-thread ldsm bases
    const uint32_t baseQ = su + Q_O + (uint32_t)((m0 + ((g & 1) << 3) + lr) * 256);
    const int aqx = g >> 1;
    const uint32_t roKV = (uint32_t)((((g >> 1) << 3) + lr) * 256);
    const int bkx = g & 1;

    float O[16][4];
#pragma unroll
    for (int i = 0; i < 16; i++)
#pragma unroll
        for (int j = 0; j < 4; j++) O[i][j] = 0.0f;
    float lsum0 = 0.0f, lsum1 = 0.0f;

    for (int t = 0; t < ntiles; t++) {
        const int cur = t & 1, nxt = cur ^ 1;

        // ---- async prefetch K(t+1), V(t+1) ----
        if (t + 1 < ntiles) {
            const __half* Kt = Kg + (size_t)(t + 1) * BK * HD;
            const __half* Vt = Vg + (size_t)(t + 1) * BK * HD;
#pragma unroll
            for (int i = 0; i < 4; i++) {
                int idx = tid + NT * i;
                int row = idx >> 4, cc = idx & 15;
                uint32_t o = row * 256 + ((cc ^ (row & 7)) << 4);
                CPA16(su + K_O + nxt * KBUF + o, Kt + row * HD + cc * 8);
                CPA16(su + V_O + nxt * VBUF + o, Vt + row * HD + cc * 8);
            }
            CPA_COMMIT();
        }

        // ---- S = Q K^T ----
        float S[8][4];
#pragma unroll
        for (int i = 0; i < 8; i++)
#pragma unroll
            for (int j = 0; j < 4; j++) S[i][j] = 0.0f;

        const uint32_t baseK = su + K_O + (uint32_t)cur * KBUF + roKV;
#pragma unroll
        for (int ks = 0; ks < 8; ks++) {
            uint32_t qf[4];
            ldsm4(qf, baseQ + (uint32_t)(((2 * ks + aqx) ^ lr) << 4));
#pragma unroll
            for (int jn = 0; jn < 4; jn++) {
                uint32_t kf[4];
                ldsm4(kf, baseK + jn * (16 * 256) + (uint32_t)(((2 * ks + bkx) ^ lr) << 4));
                mma16(S[2 * jn],     qf, kf[0], kf[1]);
                mma16(S[2 * jn + 1], qf, kf[2], kf[3]);
            }
        }

        // ---- softmax in registers -> P packed half2 ----
        uint32_t P01[8], P23[8];
        const float* mt = msm + t * BK + 2 * (lane & 3);
#pragma unroll
        for (int j = 0; j < 8; j++) {
            float2 mv = *reinterpret_cast<const float2*>(mt + 8 * j);
            float p0 = ex2f(fmaf(S[j][0], C1, mv.x));
            float p1 = ex2f(fmaf(S[j][1], C1, mv.y));
            float p2 = ex2f(fmaf(S[j][2], C1, mv.x));
            float p3 = ex2f(fmaf(S[j][3], C1, mv.y));
            __half2 h01 = __floats2half2_rn(p0, p1);
            __half2 h23 = __floats2half2_rn(p2, p3);
            float2 f01 = __half22float2(h01);
            float2 f23 = __half22float2(h23);
            lsum0 += f01.x + f01.y;
            lsum1 += f23.x + f23.y;
            P01[j] = *reinterpret_cast<uint32_t*>(&h01);
            P23[j] = *reinterpret_cast<uint32_t*>(&h23);
        }

        // ---- O += P V ----
        const uint32_t baseV = su + V_O + (uint32_t)cur * VBUF + roKV;
#pragma unroll
        for (int ks = 0; ks < 4; ks++) {
            uint32_t a[4] = {P01[2 * ks], P23[2 * ks], P01[2 * ks + 1], P23[2 * ks + 1]};
#pragma unroll
            for (int db = 0; db < 8; db++) {
                uint32_t vf[4];
                ldsm4t(vf, baseV + ks * 4096 + (uint32_t)(((2 * db + bkx) ^ lr) << 4));
                mma16(O[2 * db],     a, vf[0], vf[2]);
                mma16(O[2 * db + 1], a, vf[1], vf[3]);
            }
        }

        CPA_WAIT0();
        __syncthreads();
    }

    // ---- l reduction ----
    lsum0 += __shfl_xor_sync(0xffffffffu, lsum0, 1);
    lsum0 += __shfl_xor_sync(0xffffffffu, lsum0, 2);
    lsum1 += __shfl_xor_sync(0xffffffffu, lsum1, 1);
    lsum1 += __shfl_xor_sync(0xffffffffu, lsum1, 2);
    const float inv0 = 1.0f / lsum0;
    const float inv1 = 1.0f / lsum1;

    float* Ob0 = Out + ((size_t)b * Lq + q0 + m0 + (lane >> 2)) * HD;
    float* Ob1 = Ob0 + 8 * HD;
#pragma unroll
    for (int nb = 0; nb < 16; nb++) {
        int col = nb * 8 + 2 * (lane & 3);
        *reinterpret_cast<float2*>(Ob0 + col) = make_float2(O[nb][0] * inv0, O[nb][1] * inv0);
        *reinterpret_cast<float2*>(Ob1 + col) = make_float2(O[nb][2] * inv1, O[nb][3] * inv1);
    }
}

// ================= host launch =================
extern "C" void kernel_launch(void* const* d_in, const int* in_sizes, int n_in,
                              void* d_out, int out_size)
{
    const float* Q    = (const float*)d_in[0];
    const float* K    = (const float*)d_in[1];
    const float* V    = (const float*)d_in[2];
    const float* mask = (const float*)d_in[3];
    float* O          = (float*)d_out;

    const int Lk = in_sizes[3];
    const int B  = in_sizes[1] / (Lk * HD);
    const int Lq = in_sizes[0] / (B * HD);

    static bool attr_set = false;
    if (!attr_set) {
        cudaFuncSetAttribute(fa_cp_kernel,
                             cudaFuncAttributeMaxDynamicSharedMemorySize, SMEM_BYTES);
        attr_set = true;
    }

    const int n4 = (B * Lk * HD) / 4;
    cvt3_kernel<<<(n4 + 255) / 256, 256>>>(
        (const float4*)Q, (const float4*)K, (const float4*)V, n4);

    dim3 grid(Lq / BQ, B);
    fa_cp_kernel<<<grid, NT, SMEM_BYTES>>>(mask, O, Lq, Lk);
}

// round 9
// speedup vs baseline: 1.1754x; 1.1754x over previous
#include <cuda_runtime.h>
#include <cuda_fp16.h>
#include <cstdint>

#define NT 256
#define HD 128
#define BQ 128
#define BK 64

#define NELEM (16 * 2048 * 128)

// static device scratch (allowed; no allocation)
__device__ __half g_kh[NELEM];
__device__ __half g_vh[NELEM];
__device__ int    g_ps[2048];
__device__ float  g_cmask[2048];
__device__ int    g_total;
__device__ int    g_ntiles;

// ---- smem layout (byte offsets) ----
#define Q_O  0            // 128 rows x 256B fp16 (swizzled)      = 32768
#define K_O  32768        // 2 x [64][128] fp16 swizzled          = 32768
#define KBUF 16384
#define V_O  65536        // 2 x [64][128] fp16 swizzled          = 32768
#define VBUF 16384
#define M_O  98304        // 2048 floats, compacted additive mask = 8192
#define SMEM_BYTES 106496

__device__ __forceinline__ uint32_t smem_u32(const void* p) {
    uint32_t a;
    asm("{ .reg .u64 t; cvta.to.shared.u64 t, %1; cvt.u32.u64 %0, t; }" : "=r"(a) : "l"(p));
    return a;
}

__device__ __forceinline__ void ldsm4(uint32_t r[4], uint32_t addr) {
    asm volatile("ldmatrix.sync.aligned.m8n8.x4.shared.b16 {%0,%1,%2,%3}, [%4];"
                 : "=r"(r[0]), "=r"(r[1]), "=r"(r[2]), "=r"(r[3]) : "r"(addr));
}
__device__ __forceinline__ void ldsm4t(uint32_t r[4], uint32_t addr) {
    asm volatile("ldmatrix.sync.aligned.m8n8.x4.trans.shared.b16 {%0,%1,%2,%3}, [%4];"
                 : "=r"(r[0]), "=r"(r[1]), "=r"(r[2]), "=r"(r[3]) : "r"(addr));
}

__device__ __forceinline__ void mma16(float d[4], const uint32_t a[4],
                                      uint32_t b0, uint32_t b1) {
    asm volatile("mma.sync.aligned.m16n8k16.row.col.f32.f16.f16.f32 "
                 "{%0,%1,%2,%3}, {%4,%5,%6,%7}, {%8,%9}, {%0,%1,%2,%3};"
                 : "+f"(d[0]), "+f"(d[1]), "+f"(d[2]), "+f"(d[3])
                 : "r"(a[0]), "r"(a[1]), "r"(a[2]), "r"(a[3]), "r"(b0), "r"(b1));
}

__device__ __forceinline__ float ex2f(float x) {
    float r; asm("ex2.approx.ftz.f32 %0, %1;" : "=f"(r) : "f"(x)); return r;
}

__device__ __forceinline__ uint2 cvt4_hi(float4 f) {
    __half2 h01 = __floats2half2_rn(f.x, f.y);
    __half2 h23 = __floats2half2_rn(f.z, f.w);
    uint2 r;
    r.x = *reinterpret_cast<uint32_t*>(&h01);
    r.y = *reinterpret_cast<uint32_t*>(&h23);
    return r;
}

#define CPA16(dst, src) \
    asm volatile("cp.async.ca.shared.global [%0], [%1], 16;" :: "r"(dst), "l"(src))
#define CPA_COMMIT() asm volatile("cp.async.commit_group;")
#define CPA_WAIT0()  asm volatile("cp.async.wait_group 0;" ::: "memory")

// ============ kernel A: mask prefix-scan + compacted mask ============
__global__ void __launch_bounds__(1024, 1)
scan_kernel(const float* __restrict__ mask)
{
    __shared__ int wsum[32];
    __shared__ int s_total;
    const int tid = threadIdx.x;           // 1024 threads, 2048 elems
    const int lane = tid & 31, w = tid >> 5;

    int a = (mask[2 * tid]     < 0.5f) ? 1 : 0;
    int bb = (mask[2 * tid + 1] < 0.5f) ? 1 : 0;
    int s = a + bb;
    int inc = s;
#pragma unroll
    for (int o = 1; o < 32; o <<= 1) {
        int t = __shfl_up_sync(0xffffffffu, inc, o);
        if (lane >= o) inc += t;
    }
    if (lane == 31) wsum[w] = inc;
    __syncthreads();
    if (w == 0) {
        int v = wsum[lane];
        int vi = v;
#pragma unroll
        for (int o = 1; o < 32; o <<= 1) {
            int t = __shfl_up_sync(0xffffffffu, vi, o);
            if (lane >= o) vi += t;
        }
        wsum[lane] = vi - v;                // exclusive warp offset
        if (lane == 31) s_total = vi;
    }
    __syncthreads();

    const int base = wsum[w] + inc - s;
    g_ps[2 * tid]     = base;
    g_ps[2 * tid + 1] = base + a;

    const int total = s_total;
    if (tid == 0) { g_total = total; g_ntiles = (total + 63) >> 6; }
    const float C2 = -1.44269504088896341e9f;
    g_cmask[2 * tid]     = (2 * tid     < total) ? 0.0f : C2;
    g_cmask[2 * tid + 1] = (2 * tid + 1 < total) ? 0.0f : C2;
}

// ============ kernel B: compact + cvt K,V; zero padding rows ============
__global__ void __launch_bounds__(256, 8)
compact_kernel(const float4* __restrict__ K, const float4* __restrict__ V,
               const float* __restrict__ mask, int Lk, int B)
{
    const int i = blockIdx.x * 256 + threadIdx.x;
    const int n4 = B * Lk * (HD / 4);
    if (i < n4) {
        int row = i >> 5;                 // HD/4 = 32 float4 per row
        int c   = i & 31;
        int r   = row % Lk;
        if (mask[r] < 0.5f) {
            int batch = row / Lk;
            int dst = batch * Lk + g_ps[r];
            reinterpret_cast<uint2*>(g_kh)[dst * 32 + c] = cvt4_hi(K[i]);
            reinterpret_cast<uint2*>(g_vh)[dst * 32 + c] = cvt4_hi(V[i]);
        }
    }
    // zero-fill padding rows [total, ntiles*64) per batch
    if (i < B * 64 * 32) {
        const int total = g_total;
        const int pad = (g_ntiles << 6) - total;
        const int pr = (i >> 5) & 63;
        if (pr < pad) {
            int batch = i / (64 * 32);
            int c = i & 31;
            int dst = batch * Lk + total + pr;
            uint2 z = make_uint2(0u, 0u);
            reinterpret_cast<uint2*>(g_kh)[dst * 32 + c] = z;
            reinterpret_cast<uint2*>(g_vh)[dst * 32 + c] = z;
        }
    }
}

// ================= main kernel =================
__global__ void __launch_bounds__(NT, 2)
fa_cc_kernel(const float* __restrict__ Q, float* __restrict__ Out,
             int Lq, int Lk)
{
    extern __shared__ char sm8[];
    const uint32_t su = smem_u32(sm8);

    const int tid  = threadIdx.x;
    const int lane = tid & 31;
    const int wid  = tid >> 5;
    const int m0   = wid << 4;
    const int b    = blockIdx.y;
    const int q0   = blockIdx.x * BQ;

    const int lr = lane & 7;
    const int g  = lane >> 3;

    const float C1 = 0.0883883476483184405f * 1.44269504088896341f;

    const float*  Qb = Q + ((size_t)b * Lq + q0) * HD;
    const __half* Kg = g_kh + (size_t)b * Lk * HD;
    const __half* Vg = g_vh + (size_t)b * Lk * HD;
    const int ntiles = g_ntiles;

    // ---------------- prologue ----------------
    // K(0), V(0) via cp.async first (longest latency)
#pragma unroll
    for (int i = 0; i < 4; i++) {
        int idx = tid + NT * i;
        int row = idx >> 4, cc = idx & 15;
        uint32_t o = row * 256 + ((cc ^ (row & 7)) << 4);
        CPA16(su + K_O + o, Kg + row * HD + cc * 8);
        CPA16(su + V_O + o, Vg + row * HD + cc * 8);
    }
    CPA_COMMIT();

    // compacted mask -> smem
    float* msm = (float*)(sm8 + M_O);
#pragma unroll
    for (int i = 0; i < 8; i++)
        msm[tid + NT * i] = g_cmask[tid + NT * i];

    // Q fp32 -> fp16 swizzled smem (one-time)
#pragma unroll
    for (int i = 0; i < 16; i++) {
        int j = tid + NT * i;
        int row = j >> 5, c4 = (j & 31) << 2;
        float4 f = *reinterpret_cast<const float4*>(Qb + row * HD + c4);
        *reinterpret_cast<uint2*>(sm8 + Q_O + row * 256 +
                                  ((((c4 >> 3) ^ (row & 7)) << 4) + ((c4 & 7) << 1))) =
            cvt4_hi(f);
    }
    CPA_WAIT0();
    __syncthreads();

    // per-thread ldsm bases
    const uint32_t baseQ = su + Q_O + (uint32_t)((m0 + ((g & 1) << 3) + lr) * 256);
    const int aqx = g >> 1;
    const uint32_t roKV = (uint32_t)((((g >> 1) << 3) + lr) * 256);
    const int bkx = g & 1;

    float O[16][4];
#pragma unroll
    for (int i = 0; i < 16; i++)
#pragma unroll
        for (int j = 0; j < 4; j++) O[i][j] = 0.0f;
    float lsum0 = 0.0f, lsum1 = 0.0f;

    for (int t = 0; t < ntiles; t++) {
        const int cur = t & 1, nxt = cur ^ 1;

        // ---- async prefetch K(t+1), V(t+1) ----
        if (t + 1 < ntiles) {
            const __half* Kt = Kg + (size_t)(t + 1) * BK * HD;
            const __half* Vt = Vg + (size_t)(t + 1) * BK * HD;
#pragma unroll
            for (int i = 0; i < 4; i++) {
                int idx = tid + NT * i;
                int row = idx >> 4, cc = idx & 15;
                uint32_t o = row * 256 + ((cc ^ (row & 7)) << 4);
                CPA16(su + K_O + nxt * KBUF + o, Kt + row * HD + cc * 8);
                CPA16(su + V_O + nxt * VBUF + o, Vt + row * HD + cc * 8);
            }
            CPA_COMMIT();
        }

        // ---- S = Q K^T ----
        float S[8][4];
#pragma unroll
        for (int i = 0; i < 8; i++)
#pragma unroll
            for (int j = 0; j < 4; j++) S[i][j] = 0.0f;

        const uint32_t baseK = su + K_O + (uint32_t)cur * KBUF + roKV;
#pragma unroll
        for (int ks = 0; ks < 8; ks++) {
            uint32_t qf[4];
            ldsm4(qf, baseQ + (uint32_t)(((2 * ks + aqx) ^ lr) << 4));
#pragma unroll
            for (int jn = 0; jn < 4; jn++) {
                uint32_t kf[4];
                ldsm4(kf, baseK + jn * (16 * 256) + (uint32_t)(((2 * ks + bkx) ^ lr) << 4));
                mma16(S[2 * jn],     qf, kf[0], kf[1]);
                mma16(S[2 * jn + 1], qf, kf[2], kf[3]);
            }
        }

        // ---- softmax in registers -> P packed half2 ----
        uint32_t P01[8], P23[8];
        const float* mt = msm + t * BK + 2 * (lane & 3);
#pragma unroll
        for (int j = 0; j < 8; j++) {
            float2 mv = *reinterpret_cast<const float2*>(mt + 8 * j);
            float p0 = ex2f(fmaf(S[j][0], C1, mv.x));
            float p1 = ex2f(fmaf(S[j][1], C1, mv.y));
            float p2 = ex2f(fmaf(S[j][2], C1, mv.x));
            float p3 = ex2f(fmaf(S[j][3], C1, mv.y));
            __half2 h01 = __floats2half2_rn(p0, p1);
            __half2 h23 = __floats2half2_rn(p2, p3);
            float2 f01 = __half22float2(h01);
            float2 f23 = __half22float2(h23);
            lsum0 += f01.x + f01.y;
            lsum1 += f23.x + f23.y;
            P01[j] = *reinterpret_cast<uint32_t*>(&h01);
            P23[j] = *reinterpret_cast<uint32_t*>(&h23);
        }

        // ---- O += P V ----
        const uint32_t baseV = su + V_O + (uint32_t)cur * VBUF + roKV;
#pragma unroll
        for (int ks = 0; ks < 4; ks++) {
            uint32_t a[4] = {P01[2 * ks], P23[2 * ks], P01[2 * ks + 1], P23[2 * ks + 1]};
#pragma unroll
            for (int db = 0; db < 8; db++) {
                uint32_t vf[4];
                ldsm4t(vf, baseV + ks * 4096 + (uint32_t)(((2 * db + bkx) ^ lr) << 4));
                mma16(O[2 * db],     a, vf[0], vf[2]);
                mma16(O[2 * db + 1], a, vf[1], vf[3]);
            }
        }

        CPA_WAIT0();
        __syncthreads();
    }

    // ---- l reduction ----
    lsum0 += __shfl_xor_sync(0xffffffffu, lsum0, 1);
    lsum0 += __shfl_xor_sync(0xffffffffu, lsum0, 2);
    lsum1 += __shfl_xor_sync(0xffffffffu, lsum1, 1);
    lsum1 += __shfl_xor_sync(0xffffffffu, lsum1, 2);
    const float inv0 = 1.0f / lsum0;
    const float inv1 = 1.0f / lsum1;

    float* Ob0 = Out + ((size_t)b * Lq + q0 + m0 + (lane >> 2)) * HD;
    float* Ob1 = Ob0 + 8 * HD;
#pragma unroll
    for (int nb = 0; nb < 16; nb++) {
        int col = nb * 8 + 2 * (lane & 3);
        *reinterpret_cast<float2*>(Ob0 + col) = make_float2(O[nb][0] * inv0, O[nb][1] * inv0);
        *reinterpret_cast<float2*>(Ob1 + col) = make_float2(O[nb][2] * inv1, O[nb][3] * inv1);
    }
}

// ================= host launch =================
extern "C" void kernel_launch(void* const* d_in, const int* in_sizes, int n_in,
                              void* d_out, int out_size)
{
    const float* Q    = (const float*)d_in[0];
    const float* K    = (const float*)d_in[1];
    const float* V    = (const float*)d_in[2];
    const float* mask = (const float*)d_in[3];
    float* O          = (float*)d_out;

    const int Lk = in_sizes[3];
    const int B  = in_sizes[1] / (Lk * HD);
    const int Lq = in_sizes[0] / (B * HD);

    static bool attr_set = false;
    if (!attr_set) {
        cudaFuncSetAttribute(fa_cc_kernel,
                             cudaFuncAttributeMaxDynamicSharedMemorySize, SMEM_BYTES);
        attr_set = true;
    }

    scan_kernel<<<1, 1024>>>(mask);

    const int n4 = B * Lk * (HD / 4);
    compact_kernel<<<(n4 + 255) / 256, 256>>>(
        (const float4*)K, (const float4*)V, mask, Lk, B);

    dim3 grid(Lq / BQ, B);
    fa_cc_kernel<<<grid, NT, SMEM_BYTES>>>(Q, O, Lq, Lk);
}